// round 3
// baseline (speedup 1.0000x reference)
#include <cuda_runtime.h>
#include <cstdint>

// Problem dims (fixed by the reference)
#define NB   4
#define NN   2048
#define FIN  128
#define NH   4
#define NC   32
#define HC   128            // NH*NC
#define ROWS (NB*NN)        // 8192 flattened (b,n)
#define MAXD 128            // neighbor-list capacity per row (avg degree ~21.5)
#define NEG  0.2f

// -------- device scratch (no allocations allowed) --------
__device__ float          g_feat [ROWS*HC];    // x@W, [row][h*32+c]  (4MB)
__device__ float          g_s    [ROWS*NH];    // a_src logits
__device__ float          g_d    [ROWS*NH];    // a_dst logits
__device__ float          g_denom[ROWS*NH];    // column softmax denominators
__device__ unsigned short g_nbr  [ROWS*MAXD];  // per-row neighbor indices
__device__ int            g_cnt  [ROWS];       // per-row neighbor counts

// -------- K0: zero denominators --------
__global__ void k_zero() {
    int i = blockIdx.x * blockDim.x + threadIdx.x;
    if (i < ROWS*NH) g_denom[i] = 0.0f;
}

// -------- K1: feat = x @ W  (register-tiled: 16 nodes/block, 128 threads) --------
__global__ void k_gemm(const float* __restrict__ x, const float* __restrict__ W) {
    __shared__ float xs[16][FIN];
    const int t  = threadIdx.x;        // output column (h*32+c)
    const int n0 = blockIdx.x * 16;    // first flattened node of this tile

    for (int idx = t; idx < 16*FIN; idx += 128) {
        int m = idx >> 7, k = idx & 127;
        xs[m][k] = x[(size_t)(n0 + m)*FIN + k];
    }
    __syncthreads();

    float acc[16];
#pragma unroll
    for (int m = 0; m < 16; m++) acc[m] = 0.0f;

#pragma unroll 4
    for (int k = 0; k < FIN; k++) {
        float wv = __ldg(&W[(size_t)k*HC + t]);   // coalesced, L1-resident (64KB)
#pragma unroll
        for (int m = 0; m < 16; m++) acc[m] = fmaf(xs[m][k], wv, acc[m]);
    }
#pragma unroll
    for (int m = 0; m < 16; m++) g_feat[(size_t)(n0 + m)*HC + t] = acc[m];
}

// -------- K2: per-node attention logits s,d (one warp per node) --------
__global__ void k_attn(const float* __restrict__ asrc, const float* __restrict__ adst) {
    const int warp = threadIdx.x >> 5, lane = threadIdx.x & 31;
    const int node = blockIdx.x * 8 + warp;
    if (node >= ROWS) return;
#pragma unroll
    for (int h = 0; h < NH; h++) {
        float f  = g_feat[(size_t)node*HC + h*NC + lane];
        float vs = f * asrc[h*NC + lane];
        float vd = f * adst[h*NC + lane];
#pragma unroll
        for (int o = 16; o; o >>= 1) {
            vs += __shfl_xor_sync(0xffffffffu, vs, o);
            vd += __shfl_xor_sync(0xffffffffu, vd, o);
        }
        if (lane == 0) { g_s[node*NH + h] = vs; g_d[node*NH + h] = vd; }
    }
}

// -------- K3: scan adj row -> neighbor list; accumulate column denominators --------
// denom[b,j,h] = sum_i adj[b,i,j] * exp(lrelu(s[b,i,h] + d[b,j,h]))  (self-loop forced)
__global__ void k_edges(const float* __restrict__ adj) {
    __shared__ int cnt_s;
    __shared__ unsigned short list_s[MAXD];
    const int row = blockIdx.x;           // flattened (b,i)
    const int b   = row >> 11;
    const int i   = row & (NN - 1);
    const int t   = threadIdx.x;

    if (t == 0) cnt_s = 0;
    __syncthreads();

    const float* arow = adj + (size_t)row * NN;
    for (int j = t; j < NN; j += 256) {
        if (arow[j] != 0.0f || j == i) {   // self-loop always present
            int p = atomicAdd(&cnt_s, 1);
            if (p < MAXD) list_s[p] = (unsigned short)j;
        }
    }
    __syncthreads();

    const int cnt = min(cnt_s, MAXD);
    if (t == 0) g_cnt[row] = cnt;
    for (int k = t; k < cnt; k += 256) g_nbr[(size_t)row*MAXD + k] = list_s[k];

    // per-(neighbor,h) exp contributions into column denominators
    for (int q = t; q < cnt*NH; q += 256) {
        int k = q >> 2, h = q & 3;
        int j = list_s[k];
        int jr = (b << 11) | j;
        float a = g_s[row*NH + h] + g_d[jr*NH + h];
        float e = __expf(a > 0.0f ? a : NEG * a);
        atomicAdd(&g_denom[jr*NH + h], e);
    }
}

// -------- K4: out[row][t] = sum_k w[k,h] * feat[nbr_k][t] + bias[t] --------
__global__ void k_out(float* __restrict__ out, const float* __restrict__ bias) {
    __shared__ unsigned short list_s[MAXD];
    __shared__ float w_s[MAXD*NH];
    const int row = blockIdx.x;
    const int b   = row >> 11;
    const int t   = threadIdx.x;       // h*32+c
    const int cnt = g_cnt[row];

    for (int k = t; k < cnt; k += 128) list_s[k] = g_nbr[(size_t)row*MAXD + k];
    __syncthreads();

    for (int q = t; q < cnt*NH; q += 128) {
        int k = q >> 2, h = q & 3;
        int jr = (b << 11) | list_s[k];
        float a = g_s[row*NH + h] + g_d[jr*NH + h];
        float e = __expf(a > 0.0f ? a : NEG * a);
        w_s[q] = e / g_denom[jr*NH + h];
    }
    __syncthreads();

    const int h = t >> 5;
    const size_t bbase = (size_t)(b << 11) * HC;
    float a0 = 0.f, a1 = 0.f, a2 = 0.f, a3 = 0.f;
    int k = 0;
    for (; k + 4 <= cnt; k += 4) {      // 4 independent chains -> MLP for L2 gathers
        a0 = fmaf(w_s[(k+0)*NH + h], g_feat[bbase + (size_t)list_s[k+0]*HC + t], a0);
        a1 = fmaf(w_s[(k+1)*NH + h], g_feat[bbase + (size_t)list_s[k+1]*HC + t], a1);
        a2 = fmaf(w_s[(k+2)*NH + h], g_feat[bbase + (size_t)list_s[k+2]*HC + t], a2);
        a3 = fmaf(w_s[(k+3)*NH + h], g_feat[bbase + (size_t)list_s[k+3]*HC + t], a3);
    }
    for (; k < cnt; k++)
        a0 = fmaf(w_s[k*NH + h], g_feat[bbase + (size_t)list_s[k]*HC + t], a0);

    out[(size_t)row*HC + t] = (a0 + a1) + (a2 + a3) + bias[t];
}

// -------- launch --------
extern "C" void kernel_launch(void* const* d_in, const int* in_sizes, int n_in,
                              void* d_out, int out_size) {
    const float* x    = (const float*)d_in[0];   // [B,N,FIN]
    const float* adj  = (const float*)d_in[1];   // [B,N,N]
    const float* W    = (const float*)d_in[2];   // [FIN,HC]
    const float* asrc = (const float*)d_in[3];   // [H,C]
    const float* adst = (const float*)d_in[4];   // [H,C]
    const float* bias = (const float*)d_in[5];   // [HC]
    float* out = (float*)d_out;                  // [B,N,HC]

    k_zero <<<(ROWS*NH + 255)/256, 256>>>();
    k_gemm <<<ROWS/16, 128>>>(x, W);
    k_attn <<<ROWS/8, 256>>>(asrc, adst);
    k_edges<<<ROWS, 256>>>(adj);
    k_out  <<<ROWS, 128>>>(out, bias);
}

// round 5
// speedup vs baseline: 1.1819x; 1.1819x over previous
#include <cuda_runtime.h>
#include <cstdint>

// Problem dims (fixed by the reference)
#define NB   4
#define NN   2048
#define FIN  128
#define NH   4
#define NC   32
#define HC   128            // NH*NC
#define ROWS (NB*NN)        // 8192 flattened (b,n)
#define MAXD 128            // neighbor-list capacity per row (avg degree ~21.5)
#define NEG  0.2f
#define XST  20             // xs row stride (floats): 16B-aligned, 4-way-conflict writes

// -------- device scratch (no allocations allowed) --------
__device__ float          g_feat [ROWS*HC];    // x@W, [row][h*32+c]  (4MB)
__device__ float          g_s    [ROWS*NH];    // a_src logits
__device__ float          g_d    [ROWS*NH];    // a_dst logits
__device__ float          g_denom[ROWS*NH];    // column softmax denominators
__device__ unsigned short g_nbr  [ROWS*MAXD];  // per-row neighbor indices
__device__ int            g_cnt  [ROWS];       // per-row neighbor counts

// -------- K0: zero denominators --------
__global__ void k_zero() {
    int i = blockIdx.x * blockDim.x + threadIdx.x;
    if (i < ROWS*NH) g_denom[i] = 0.0f;
}

// -------- K1: feat = x @ W  + fused attention logits --------
// 16 nodes/block, 128 threads (thread t = output column h*32+c).
// xs stored transposed [k][m] so the inner loop reads 4 m-values per LDS.128
// (broadcast across the warp -> conflict-free).
__global__ void __launch_bounds__(128) k_gemm(
        const float* __restrict__ x, const float* __restrict__ W,
        const float* __restrict__ asrc, const float* __restrict__ adst) {
    __shared__ float xs[FIN * XST];    // [k][m], stride XST, 10KB
    const int t  = threadIdx.x;
    const int n0 = blockIdx.x * 16;

    // coalesced load: consecutive t -> consecutive k, same m
    for (int idx = t; idx < 16*FIN; idx += 128) {
        int m = idx >> 7, k = idx & 127;
        xs[k*XST + m] = x[(size_t)(n0 + m)*FIN + k];
    }
    __syncthreads();

    float acc[16];
#pragma unroll
    for (int m = 0; m < 16; m++) acc[m] = 0.0f;

#pragma unroll 4
    for (int k = 0; k < FIN; k++) {
        float wv = __ldg(&W[(size_t)k*HC + t]);
        const float4* xv = (const float4*)&xs[k*XST];
#pragma unroll
        for (int g = 0; g < 4; g++) {
            float4 xm = xv[g];
            acc[g*4+0] = fmaf(xm.x, wv, acc[g*4+0]);
            acc[g*4+1] = fmaf(xm.y, wv, acc[g*4+1]);
            acc[g*4+2] = fmaf(xm.z, wv, acc[g*4+2]);
            acc[g*4+3] = fmaf(xm.w, wv, acc[g*4+3]);
        }
    }

    // store feat (coalesced, 512B per m)
#pragma unroll
    for (int m = 0; m < 16; m++)
        g_feat[(size_t)(n0 + m)*HC + t] = acc[m];

    // fused attention logits: warp w == head h, lane == channel c
    const int h = t >> 5, lane = t & 31;
    const float as = asrc[h*NC + lane];
    const float ad = adst[h*NC + lane];
#pragma unroll
    for (int m = 0; m < 16; m++) {
        float vs = acc[m] * as;
        float vd = acc[m] * ad;
#pragma unroll
        for (int o = 16; o; o >>= 1) {
            vs += __shfl_xor_sync(0xffffffffu, vs, o);
            vd += __shfl_xor_sync(0xffffffffu, vd, o);
        }
        if (lane == 0) {
            g_s[(n0 + m)*NH + h] = vs;
            g_d[(n0 + m)*NH + h] = vd;
        }
    }
}

// -------- K2: scan adj row -> neighbor list; accumulate column denominators --------
// Branch-free batched load: 512 threads x one float4 each = full 2048-float row,
// all LDG.128 issued before any processing (max MLP).
__global__ void __launch_bounds__(512) k_edges(const float4* __restrict__ adj4) {
    __shared__ int cnt_s;
    __shared__ unsigned short list_s[MAXD];
    const int row = blockIdx.x;           // flattened (b,i)
    const int b   = row >> 11;
    const int i   = row & (NN - 1);
    const int t   = threadIdx.x;

    if (t == 0) cnt_s = 0;

    // unconditional batched load (no dependent branch before it)
    float4 v = adj4[(size_t)row * (NN/4) + t];
    __syncthreads();   // after the load is issued; covers cnt_s init

    const int j0 = t * 4;
    float vals[4] = {v.x, v.y, v.z, v.w};
#pragma unroll
    for (int c = 0; c < 4; c++) {
        int j = j0 + c;
        if (vals[c] != 0.0f || j == i) {   // self-loop always present
            int p = atomicAdd(&cnt_s, 1);
            if (p < MAXD) list_s[p] = (unsigned short)j;
        }
    }
    __syncthreads();

    const int cnt = min(cnt_s, MAXD);
    if (t == 0) g_cnt[row] = cnt;
    if (t < cnt) g_nbr[(size_t)row*MAXD + t] = list_s[t];

    // per-(neighbor,h) exp contributions into column denominators
    for (int q = t; q < cnt*NH; q += 512) {
        int k = q >> 2, h = q & 3;
        int j = list_s[k];
        int jr = (b << 11) | j;
        float a = g_s[row*NH + h] + g_d[jr*NH + h];
        float e = __expf(a > 0.0f ? a : NEG * a);
        atomicAdd(&g_denom[jr*NH + h], e);
    }
}

// -------- K3: out[row][t] = sum_k w[k,h] * feat[nbr_k][t] + bias[t] --------
__global__ void __launch_bounds__(128) k_out(float* __restrict__ out,
                                             const float* __restrict__ bias) {
    __shared__ unsigned short list_s[MAXD];
    __shared__ float w_s[MAXD*NH];
    const int row = blockIdx.x;
    const int b   = row >> 11;
    const int t   = threadIdx.x;       // h*32+c
    const int cnt = g_cnt[row];

    if (t < cnt) list_s[t] = g_nbr[(size_t)row*MAXD + t];
    __syncthreads();

    for (int q = t; q < cnt*NH; q += 128) {
        int k = q >> 2, h = q & 3;
        int jr = (b << 11) | list_s[k];
        float a = g_s[row*NH + h] + g_d[jr*NH + h];
        float e = __expf(a > 0.0f ? a : NEG * a);
        w_s[q] = e / g_denom[jr*NH + h];
    }
    __syncthreads();

    const int h = t >> 5;
    const size_t bbase = (size_t)(b << 11) * HC;
    float a0 = 0.f, a1 = 0.f, a2 = 0.f, a3 = 0.f;
    int k = 0;
    for (; k + 4 <= cnt; k += 4) {      // 4 independent chains -> MLP for L2 gathers
        a0 = fmaf(w_s[(k+0)*NH + h], g_feat[bbase + (size_t)list_s[k+0]*HC + t], a0);
        a1 = fmaf(w_s[(k+1)*NH + h], g_feat[bbase + (size_t)list_s[k+1]*HC + t], a1);
        a2 = fmaf(w_s[(k+2)*NH + h], g_feat[bbase + (size_t)list_s[k+2]*HC + t], a2);
        a3 = fmaf(w_s[(k+3)*NH + h], g_feat[bbase + (size_t)list_s[k+3]*HC + t], a3);
    }
    for (; k < cnt; k++)
        a0 = fmaf(w_s[k*NH + h], g_feat[bbase + (size_t)list_s[k]*HC + t], a0);

    out[(size_t)row*HC + t] = (a0 + a1) + (a2 + a3) + bias[t];
}

// -------- launch --------
extern "C" void kernel_launch(void* const* d_in, const int* in_sizes, int n_in,
                              void* d_out, int out_size) {
    const float* x    = (const float*)d_in[0];   // [B,N,FIN]
    const float* adj  = (const float*)d_in[1];   // [B,N,N]
    const float* W    = (const float*)d_in[2];   // [FIN,HC]
    const float* asrc = (const float*)d_in[3];   // [H,C]
    const float* adst = (const float*)d_in[4];   // [H,C]
    const float* bias = (const float*)d_in[5];   // [HC]
    float* out = (float*)d_out;                  // [B,N,HC]

    k_zero <<<(ROWS*NH + 255)/256, 256>>>();
    k_gemm <<<ROWS/16, 128>>>(x, W, asrc, adst);
    k_edges<<<ROWS, 512>>>((const float4*)adj);
    k_out  <<<ROWS, 128>>>(out, bias);
}

// round 6
// speedup vs baseline: 1.2683x; 1.0731x over previous
#include <cuda_runtime.h>
#include <cstdint>

// Problem dims (fixed by the reference)
#define NB   4
#define NN   2048
#define FIN  128
#define NH   4
#define NC   32
#define HC   128            // NH*NC
#define ROWS (NB*NN)        // 8192 flattened (b,n)
#define MAXD 128            // neighbor-list capacity per row (avg degree ~21.5)
#define NEG  0.2f
#define XST  20             // xs row stride (floats): 16B-aligned, 4-way-conflict writes

// -------- device scratch (no allocations allowed) --------
__device__ float          g_feat [ROWS*HC];    // x@W, [row][h*32+c]  (4MB)
__device__ float          g_s    [ROWS*NH];    // a_src logits
__device__ float          g_d    [ROWS*NH];    // a_dst logits
__device__ float          g_denom[ROWS*NH];    // column softmax denominators
__device__ unsigned short g_nbr  [ROWS*MAXD];  // per-row neighbor indices
__device__ int            g_cnt  [ROWS];       // per-row neighbor counts

// -------- K1: feat = x @ W  + fused attention logits + fused denom zeroing --------
__global__ void __launch_bounds__(128) k_gemm(
        const float* __restrict__ x, const float* __restrict__ W,
        const float* __restrict__ asrc, const float* __restrict__ adst) {
    __shared__ float xs[FIN * XST];    // [k][m], stride XST
    const int t  = threadIdx.x;
    const int n0 = blockIdx.x * 16;

    // fused: zero softmax denominators (first 256 blocks cover 32K floats)
    {
        int z = blockIdx.x * 128 + t;
        if (z < ROWS*NH) g_denom[z] = 0.0f;
    }

    // coalesced load: consecutive t -> consecutive k, same m
    for (int idx = t; idx < 16*FIN; idx += 128) {
        int m = idx >> 7, k = idx & 127;
        xs[k*XST + m] = x[(size_t)(n0 + m)*FIN + k];
    }
    __syncthreads();

    float acc[16];
#pragma unroll
    for (int m = 0; m < 16; m++) acc[m] = 0.0f;

#pragma unroll 4
    for (int k = 0; k < FIN; k++) {
        float wv = __ldg(&W[(size_t)k*HC + t]);
        const float4* xv = (const float4*)&xs[k*XST];
#pragma unroll
        for (int g = 0; g < 4; g++) {
            float4 xm = xv[g];
            acc[g*4+0] = fmaf(xm.x, wv, acc[g*4+0]);
            acc[g*4+1] = fmaf(xm.y, wv, acc[g*4+1]);
            acc[g*4+2] = fmaf(xm.z, wv, acc[g*4+2]);
            acc[g*4+3] = fmaf(xm.w, wv, acc[g*4+3]);
        }
    }

#pragma unroll
    for (int m = 0; m < 16; m++)
        g_feat[(size_t)(n0 + m)*HC + t] = acc[m];

    // fused attention logits: warp w == head h, lane == channel c
    const int h = t >> 5, lane = t & 31;
    const float as = asrc[h*NC + lane];
    const float ad = adst[h*NC + lane];
#pragma unroll
    for (int m = 0; m < 16; m++) {
        float vs = acc[m] * as;
        float vd = acc[m] * ad;
#pragma unroll
        for (int o = 16; o; o >>= 1) {
            vs += __shfl_xor_sync(0xffffffffu, vs, o);
            vd += __shfl_xor_sync(0xffffffffu, vd, o);
        }
        if (lane == 0) {
            g_s[(n0 + m)*NH + h] = vs;
            g_d[(n0 + m)*NH + h] = vd;
        }
    }
}

// -------- K2: scan adj row -> neighbor list; accumulate column denominators --------
__global__ void __launch_bounds__(512) k_edges(const float4* __restrict__ adj4) {
    __shared__ int cnt_s;
    __shared__ unsigned short list_s[MAXD];
    const int row = blockIdx.x;           // flattened (b,i)
    const int b   = row >> 11;
    const int i   = row & (NN - 1);
    const int t   = threadIdx.x;

    if (t == 0) cnt_s = 0;

    // unconditional batched load (no dependent branch before it)
    float4 v = adj4[(size_t)row * (NN/4) + t];
    __syncthreads();

    const int j0 = t * 4;
    float vals[4] = {v.x, v.y, v.z, v.w};
#pragma unroll
    for (int c = 0; c < 4; c++) {
        int j = j0 + c;
        if (vals[c] != 0.0f || j == i) {   // self-loop always present
            int p = atomicAdd(&cnt_s, 1);
            if (p < MAXD) list_s[p] = (unsigned short)j;
        }
    }
    __syncthreads();

    const int cnt = min(cnt_s, MAXD);
    if (t == 0) g_cnt[row] = cnt;
    if (t < cnt) g_nbr[(size_t)row*MAXD + t] = list_s[t];

    for (int q = t; q < cnt*NH; q += 512) {
        int k = q >> 2, h = q & 3;
        int j = list_s[k];
        int jr = (b << 11) | j;
        float a = g_s[row*NH + h] + g_d[jr*NH + h];
        float e = __expf(a > 0.0f ? a : NEG * a);
        atomicAdd(&g_denom[jr*NH + h], e);
    }
}

// -------- K3: warp-per-row float4 gather --------
// lane l owns channels [4l,4l+3], head h = l>>3. One LDG.128 per (neighbor,lane).
#define OW 8   // rows (warps) per block
__global__ void __launch_bounds__(32*OW) k_out(float4* __restrict__ out,
                                               const float* __restrict__ bias) {
    __shared__ unsigned short list_s[OW][MAXD];
    __shared__ float w_s[OW][MAXD*NH];     // [k*4+h]
    const int warp = threadIdx.x >> 5, lane = threadIdx.x & 31;
    const int row  = blockIdx.x * OW + warp;
    const int b    = row >> 11;
    const int cnt  = g_cnt[row];           // broadcast load

    unsigned short* list = list_s[warp];
    float*          w    = w_s[warp];

    for (int k = lane; k < cnt; k += 32) list[k] = g_nbr[(size_t)row*MAXD + k];
    __syncwarp();

    // per-(neighbor,head) weights
    for (int q = lane; q < cnt*NH; q += 32) {
        int k = q >> 2, h = q & 3;
        int jr = (b << 11) | list[k];
        float a = g_s[row*NH + h] + g_d[jr*NH + h];
        float e = __expf(a > 0.0f ? a : NEG * a);
        w[q] = __fdividef(e, g_denom[jr*NH + h]);
    }
    __syncwarp();

    const int h4 = (lane >> 3) & 3;        // head for this lane's channel group
    const float4* feat4 = (const float4*)g_feat;
    const size_t bbase = (size_t)(b << 11) * 32;   // float4 units per row = 32

    float4 a0 = {0,0,0,0}, a1 = {0,0,0,0}, a2 = {0,0,0,0}, a3 = {0,0,0,0};
    int k = 0;
    for (; k + 4 <= cnt; k += 4) {
        int j0 = list[k+0], j1 = list[k+1], j2 = list[k+2], j3 = list[k+3];
        float4 f0 = feat4[bbase + (size_t)j0*32 + lane];
        float4 f1 = feat4[bbase + (size_t)j1*32 + lane];
        float4 f2 = feat4[bbase + (size_t)j2*32 + lane];
        float4 f3 = feat4[bbase + (size_t)j3*32 + lane];
        float w0 = w[(k+0)*NH + h4], w1 = w[(k+1)*NH + h4];
        float w2 = w[(k+2)*NH + h4], w3 = w[(k+3)*NH + h4];
        a0.x = fmaf(w0, f0.x, a0.x); a0.y = fmaf(w0, f0.y, a0.y);
        a0.z = fmaf(w0, f0.z, a0.z); a0.w = fmaf(w0, f0.w, a0.w);
        a1.x = fmaf(w1, f1.x, a1.x); a1.y = fmaf(w1, f1.y, a1.y);
        a1.z = fmaf(w1, f1.z, a1.z); a1.w = fmaf(w1, f1.w, a1.w);
        a2.x = fmaf(w2, f2.x, a2.x); a2.y = fmaf(w2, f2.y, a2.y);
        a2.z = fmaf(w2, f2.z, a2.z); a2.w = fmaf(w2, f2.w, a2.w);
        a3.x = fmaf(w3, f3.x, a3.x); a3.y = fmaf(w3, f3.y, a3.y);
        a3.z = fmaf(w3, f3.z, a3.z); a3.w = fmaf(w3, f3.w, a3.w);
    }
    for (; k < cnt; k++) {
        int j = list[k];
        float4 f = feat4[bbase + (size_t)j*32 + lane];
        float wv = w[k*NH + h4];
        a0.x = fmaf(wv, f.x, a0.x); a0.y = fmaf(wv, f.y, a0.y);
        a0.z = fmaf(wv, f.z, a0.z); a0.w = fmaf(wv, f.w, a0.w);
    }

    const float4 bv = ((const float4*)bias)[lane];
    float4 r;
    r.x = (a0.x + a1.x) + (a2.x + a3.x) + bv.x;
    r.y = (a0.y + a1.y) + (a2.y + a3.y) + bv.y;
    r.z = (a0.z + a1.z) + (a2.z + a3.z) + bv.z;
    r.w = (a0.w + a1.w) + (a2.w + a3.w) + bv.w;
    out[(size_t)row*32 + lane] = r;
}

// -------- launch --------
extern "C" void kernel_launch(void* const* d_in, const int* in_sizes, int n_in,
                              void* d_out, int out_size) {
    const float* x    = (const float*)d_in[0];   // [B,N,FIN]
    const float* adj  = (const float*)d_in[1];   // [B,N,N]
    const float* W    = (const float*)d_in[2];   // [FIN,HC]
    const float* asrc = (const float*)d_in[3];   // [H,C]
    const float* adst = (const float*)d_in[4];   // [H,C]
    const float* bias = (const float*)d_in[5];   // [HC]
    float4* out = (float4*)d_out;                // [B,N,HC]

    k_gemm <<<ROWS/16, 128>>>(x, W, asrc, adst);   // also zeros g_denom
    k_edges<<<ROWS, 512>>>((const float4*)adj);
    k_out  <<<ROWS/OW, 32*OW>>>(out, bias);
}